// round 4
// baseline (speedup 1.0000x reference)
#include <cuda_runtime.h>

typedef unsigned long long ull;

#define BS   8
#define NPTS 1024
#define JJ   3
#define FIN  32
#define KIN  96
#define FOUT 64
#define ROWS (BS*NPTS)
#define MC   16
#define NCHUNK (NPTS/MC)
#define PWW  52            // ww_s row pitch (floats), 16B-aligned rows, rows 8 banks apart
#define PXF  36            // x row pitch (floats),   16B-aligned rows, rows 4 banks apart
#define BLKN 64
#define NTILE (NPTS/BLKN)
#define PYT  68            // yT pitch (floats), 16B-aligned rows
#define WWFL (BLKN*PWW)    // 3328 floats per ww buffer
#define XFL  (FIN*PXF)     // 1152 floats per x buffer

__device__ __align__(16) float g_wt[KIN*FOUT];
__device__ float g_psum[(ROWS/64)*FOUT];
__device__ float g_psq [(ROWS/64)*FOUT];
__device__ float g_coef[2*FOUT];

__device__ __forceinline__ ull fma2(ull a, ull b, ull c) {
    ull d;
    asm("fma.rn.f32x2 %0, %1, %2, %3;" : "=l"(d) : "l"(a), "l"(b), "l"(c));
    return d;
}
__device__ __forceinline__ float hsum2(ull v) {
    union { ull u; float f[2]; } cv; cv.u = v;
    return cv.f[0] + cv.f[1];
}
__device__ __forceinline__ ull dup2(float x) {
    unsigned b = __float_as_uint(x);
    return (((ull)b) << 32) | (ull)b;
}

// K0: fuse/transpose W1,W2 -> g_wt[k][col]
__global__ void k0_wt(const float* __restrict__ W1, const float* __restrict__ W2) {
    int t = blockIdx.x * 256 + threadIdx.x;
    if (t < KIN * FOUT) {
        int c = t & 63, k = t >> 6;
        g_wt[k * FOUT + c] = (c < 32) ? W1[c * KIN + k] : W2[(c - 32) * KIN + k];
    }
}

// Fused: GMul (y = sum_m WW*x) -> MLP(relu/lin) -> Z + BN partial sums
__global__ __launch_bounds__(256) void k_fused(const float* __restrict__ WW,
                                               const float* __restrict__ X,
                                               const float* __restrict__ b1,
                                               const float* __restrict__ b2,
                                               float* __restrict__ Z) {
    __shared__ __align__(16) float sbuf[2*WWFL + 2*XFL];   // 35840 B
    __shared__ float ps[4*FOUT], pq[4*FOUT];

    float* wwbuf[2] = { sbuf, sbuf + WWFL };
    float* xsbuf[2] = { sbuf + 2*WWFL, sbuf + 2*WWFL + XFL };
    float* yT = sbuf;   // overlays ww/x buffers after phase A

    const int t  = threadIdx.x;
    const int b  = blockIdx.y;
    const int n0 = blockIdx.x * BLKN;
    const float* wwB = WW + (size_t)(b * NPTS + n0) * (NPTS * JJ);
    const float* xB  = X + (size_t)b * NPTS * FIN;

    const int lane = t & 31, warp = t >> 5;
    const int fq = lane & 7, nq = lane >> 3;
    const int nloc = warp * 8 + nq * 2;

    ull acc[2][3][4];
#pragma unroll
    for (int a = 0; a < 2; a++)
#pragma unroll
        for (int j = 0; j < 3; j++)
#pragma unroll
            for (int k = 0; k < 4; k++) acc[a][j][k] = 0ULL;

    // loader indices: 768 float4 of WW per chunk, 3 per thread
    int goff[3], soff[3][4];
#pragma unroll
    for (int i = 0; i < 3; i++) {
        int flat = i * 256 + t;
        int n = flat / 12, mj4 = flat % 12;
        goff[i] = n * (NPTS * JJ) + mj4 * 4;
#pragma unroll
        for (int k = 0; k < 4; k++) {
            int mj = mj4 * 4 + k;
            int m = mj / 3, j = mj - m * 3;
            soff[i][k] = n * PWW + j * MC + m;
        }
    }
    const bool xact = t < 128;
    const int  xm = t >> 3, xf = (t & 7) * 4;
    const int  xgoff = xm * FIN + xf;

    // prologue: chunk 0 into registers
    float4 wr0, wr1, wr2, xr;
    wr0 = *(const float4*)(wwB + goff[0]);
    wr1 = *(const float4*)(wwB + goff[1]);
    wr2 = *(const float4*)(wwB + goff[2]);
    xr  = xact ? *(const float4*)(xB + xgoff) : make_float4(0.f,0.f,0.f,0.f);

    for (int c = 0; c < NCHUNK; ++c) {
        float* wwb = wwbuf[c & 1];
        float* xsb = xsbuf[c & 1];

        wwb[soff[0][0]] = wr0.x; wwb[soff[0][1]] = wr0.y;
        wwb[soff[0][2]] = wr0.z; wwb[soff[0][3]] = wr0.w;
        wwb[soff[1][0]] = wr1.x; wwb[soff[1][1]] = wr1.y;
        wwb[soff[1][2]] = wr1.z; wwb[soff[1][3]] = wr1.w;
        wwb[soff[2][0]] = wr2.x; wwb[soff[2][1]] = wr2.y;
        wwb[soff[2][2]] = wr2.z; wwb[soff[2][3]] = wr2.w;
        if (xact) {
            xsb[(xf + 0) * PXF + xm] = xr.x;
            xsb[(xf + 1) * PXF + xm] = xr.y;
            xsb[(xf + 2) * PXF + xm] = xr.z;
            xsb[(xf + 3) * PXF + xm] = xr.w;
        }

        if (c + 1 < NCHUNK) {   // issue next chunk's gmem loads (hidden by compute)
            const float* p = wwB + (c + 1) * (MC * JJ);
            wr0 = *(const float4*)(p + goff[0]);
            wr1 = *(const float4*)(p + goff[1]);
            wr2 = *(const float4*)(p + goff[2]);
            if (xact) xr = *(const float4*)(xB + (c + 1) * MC * FIN + xgoff);
        }
        __syncthreads();

#pragma unroll
        for (int mp2 = 0; mp2 < 4; ++mp2) {
            ulonglong2 xv[4];
#pragma unroll
            for (int k = 0; k < 4; k++)
                xv[k] = *(const ulonglong2*)(xsb + (fq + 8*k) * PXF + 4*mp2);
#pragma unroll
            for (int nn = 0; nn < 2; nn++) {
                const float* rp = wwb + (nloc + nn) * PWW + 4*mp2;
                ulonglong2 w0 = *(const ulonglong2*)(rp);
                ulonglong2 w1 = *(const ulonglong2*)(rp + MC);
                ulonglong2 w2 = *(const ulonglong2*)(rp + 2*MC);
#pragma unroll
                for (int k = 0; k < 4; k++) {
                    acc[nn][0][k] = fma2(w0.x, xv[k].x, acc[nn][0][k]);
                    acc[nn][0][k] = fma2(w0.y, xv[k].y, acc[nn][0][k]);
                    acc[nn][1][k] = fma2(w1.x, xv[k].x, acc[nn][1][k]);
                    acc[nn][1][k] = fma2(w1.y, xv[k].y, acc[nn][1][k]);
                    acc[nn][2][k] = fma2(w2.x, xv[k].x, acc[nn][2][k]);
                    acc[nn][2][k] = fma2(w2.y, xv[k].y, acc[nn][2][k]);
                }
            }
        }
    }
    __syncthreads();   // all reads of ww/x buffers done before yT overlays them

    // write y tile transposed into smem: yT[kin][row]
#pragma unroll
    for (int nn = 0; nn < 2; nn++)
#pragma unroll
        for (int j = 0; j < 3; j++)
#pragma unroll
            for (int k = 0; k < 4; k++)
                yT[(j * FIN + fq + 8*k) * PYT + nloc + nn] = hsum2(acc[nn][j][k]);
    __syncthreads();

    // phase B: z = [relu(y@W1^T+b1), y@W2^T+b2]
    const int col = t & 63, rg = t >> 6;
    const int rbase = rg * 16;
    ull acc2[8];
#pragma unroll
    for (int q = 0; q < 8; q++) acc2[q] = 0ULL;

#pragma unroll 4
    for (int k = 0; k < KIN; k++) {
        ull wd = dup2(__ldg(&g_wt[k * FOUT + col]));
        const float* yp = yT + k * PYT + rbase;
#pragma unroll
        for (int q = 0; q < 4; q++) {
            ulonglong2 yv = *(const ulonglong2*)(yp + 4*q);
            acc2[2*q]     = fma2(yv.x, wd, acc2[2*q]);
            acc2[2*q + 1] = fma2(yv.y, wd, acc2[2*q + 1]);
        }
    }

    const float bias = (col < 32) ? __ldg(&b1[col]) : __ldg(&b2[col - 32]);
    const size_t row0 = (size_t)(b * NPTS + n0);
    float s = 0.f, sq = 0.f;
#pragma unroll
    for (int q = 0; q < 4; q++)
#pragma unroll
        for (int p = 0; p < 2; p++) {
            union { ull u; float f[2]; } cv; cv.u = acc2[2*q + p];
#pragma unroll
            for (int h = 0; h < 2; h++) {
                float z = cv.f[h] + bias;
                if (col < 32) z = fmaxf(z, 0.f);
                int lr = rbase + 4*q + 2*p + h;
                Z[(row0 + lr) * FOUT + col] = z;
                s += z; sq += z * z;
            }
        }
    ps[rg * FOUT + col] = s; pq[rg * FOUT + col] = sq;
    __syncthreads();
    if (rg == 0) {   // fixed-order combine: deterministic
        float S = ps[col] + ps[FOUT + col] + ps[2*FOUT + col] + ps[3*FOUT + col];
        float Q = pq[col] + pq[FOUT + col] + pq[2*FOUT + col] + pq[3*FOUT + col];
        int blk = b * NTILE + blockIdx.x;
        g_psum[blk * FOUT + col] = S;
        g_psq [blk * FOUT + col] = Q;
    }
}

// K3: parallel deterministic reduce of 128 block partials -> scale/shift
__global__ void k3_stats(const float* __restrict__ gamma, const float* __restrict__ beta) {
    __shared__ float rs[16*FOUT], rq[16*FOUT];
    int t = threadIdx.x;          // 1024 threads
    int col = t & 63, seg = t >> 6;   // 16 segments x 8 blocks each
    float S = 0.f, Q = 0.f;
#pragma unroll
    for (int i = 0; i < 8; i++) {
        int idx = (seg * 8 + i) * FOUT + col;
        S += g_psum[idx];
        Q += g_psq [idx];
    }
    rs[seg * FOUT + col] = S; rq[seg * FOUT + col] = Q;
    __syncthreads();
    for (int h = 8; h > 0; h >>= 1) {
        if (seg < h) {
            rs[seg * FOUT + col] += rs[(seg + h) * FOUT + col];
            rq[seg * FOUT + col] += rq[(seg + h) * FOUT + col];
        }
        __syncthreads();
    }
    if (seg == 0) {
        float mean = rs[col] * (1.0f / ROWS);
        float var  = rq[col] * (1.0f / ROWS) - mean * mean;
        float sc   = gamma[col] * rsqrtf(var + 1e-5f);
        g_coef[col]        = sc;
        g_coef[FOUT + col] = beta[col] - mean * sc;
    }
}

// K4: in-place normalize
__global__ __launch_bounds__(256) void k4_norm(float* __restrict__ Z) {
    int idx = blockIdx.x * 256 + threadIdx.x;   // float4 index
    float4 v = ((float4*)Z)[idx];
    int c = (idx & 15) * 4;
    v.x = v.x * g_coef[c]     + g_coef[FOUT + c];
    v.y = v.y * g_coef[c + 1] + g_coef[FOUT + c + 1];
    v.z = v.z * g_coef[c + 2] + g_coef[FOUT + c + 2];
    v.w = v.w * g_coef[c + 3] + g_coef[FOUT + c + 3];
    ((float4*)Z)[idx] = v;
}

extern "C" void kernel_launch(void* const* d_in, const int* in_sizes, int n_in,
                              void* d_out, int out_size) {
    const float* WW    = (const float*)d_in[0];
    const float* X     = (const float*)d_in[1];
    const float* W1    = (const float*)d_in[2];
    const float* b1    = (const float*)d_in[3];
    const float* W2    = (const float*)d_in[4];
    const float* b2    = (const float*)d_in[5];
    const float* gamma = (const float*)d_in[6];
    const float* beta  = (const float*)d_in[7];
    float* Z = (float*)d_out;

    k0_wt<<<(KIN * FOUT + 255) / 256, 256>>>(W1, W2);
    dim3 g1(NTILE, BS);
    k_fused<<<g1, 256>>>(WW, X, b1, b2, Z);
    k3_stats<<<1, 1024>>>(gamma, beta);
    k4_norm<<<(ROWS * FOUT / 4) / 256, 256>>>(Z);
}

// round 5
// speedup vs baseline: 1.1919x; 1.1919x over previous
#include <cuda_runtime.h>

typedef unsigned long long ull;

#define BS   8
#define NPTS 1024
#define JJ   3
#define FIN  32
#define KIN  96
#define FOUT 64
#define ROWS (BS*NPTS)
#define MC   16
#define NCHUNK (NPTS/MC)     // 64
#define KS   4               // k-split
#define CPB  (NCHUNK/KS)     // 16 chunks per block
#define PWW  50
#define PX2  17
#define BLKN 64
#define NTILE (NPTS/BLKN)    // 16
#define PYT2 36              // k2 yT pitch (32 rows + pad), 16B aligned
#define K2ROWS 32
#define NBLK2 (ROWS/K2ROWS)  // 256

__device__ __align__(16) float g_yp[KS*ROWS*KIN];     // 12.6 MB partial y
__device__ __align__(16) float g_wt[KIN*FOUT];
__device__ float g_psum[NBLK2*FOUT];
__device__ float g_psq [NBLK2*FOUT];
__device__ float g_coef[2*FOUT];

__device__ __forceinline__ ull fma2(ull a, ull b, ull c) {
    ull d;
    asm("fma.rn.f32x2 %0, %1, %2, %3;" : "=l"(d) : "l"(a), "l"(b), "l"(c));
    return d;
}
__device__ __forceinline__ ull ld64s(const float* p) {
    return *reinterpret_cast<const ull*>(p);
}
__device__ __forceinline__ float hsum2(ull v) {
    union { ull u; float f[2]; } cv; cv.u = v;
    return cv.f[0] + cv.f[1];
}
__device__ __forceinline__ ull dup2(float x) {
    unsigned b = __float_as_uint(x);
    return (((ull)b) << 32) | (ull)b;
}

// K0: fuse/transpose W1,W2 -> g_wt[k][col]
__global__ void k0_wt(const float* __restrict__ W1, const float* __restrict__ W2) {
    int t = blockIdx.x * 256 + threadIdx.x;
    if (t < KIN * FOUT) {
        int c = t & 63, k = t >> 6;
        g_wt[k * FOUT + c] = (c < 32) ? W1[c * KIN + k] : W2[(c - 32) * KIN + k];
    }
}

// K1: partial y over m-segment; identical mainloop to the measured R2 kernel.
__global__ __launch_bounds__(256) void k1_gmul(const float* __restrict__ WW,
                                               const float* __restrict__ X) {
    __shared__ __align__(16) float ww_s[BLKN * PWW];   // [n][j*MC+m]
    __shared__ __align__(16) ull   x2_s[FIN * PX2];    // [f][m-pair]

    const int t  = threadIdx.x;
    const int b  = blockIdx.y;
    const int n0 = blockIdx.x * BLKN;
    const int c0 = blockIdx.z * CPB;
    const float* wwB = WW + (size_t)(b * NPTS + n0) * (NPTS * JJ);
    const float* xB  = X + (size_t)b * NPTS * FIN;

    const int lane = t & 31, warp = t >> 5;
    const int fq = lane & 7, nq = lane >> 3;
    const int nloc = warp * 8 + nq * 2;

    ull acc[2][3][4];
#pragma unroll
    for (int a = 0; a < 2; a++)
#pragma unroll
        for (int j = 0; j < 3; j++)
#pragma unroll
            for (int k = 0; k < 4; k++) acc[a][j][k] = 0ULL;

    int goff[3], soff[3][4];
#pragma unroll
    for (int i = 0; i < 3; i++) {
        int flat = i * 256 + t;
        int n = flat / 12, mj4 = flat % 12;
        goff[i] = n * (NPTS * JJ) + mj4 * 4;
#pragma unroll
        for (int k = 0; k < 4; k++) {
            int mj = mj4 * 4 + k;
            int m = mj / 3, j = mj - m * 3;
            soff[i][k] = n * PWW + j * MC + m;
        }
    }
    const bool xact = t < 128;
    const int  xm = t >> 3, xf = (t & 7) * 4;
    const int  xgoff = xm * FIN + xf;
    int xsoff[4];
#pragma unroll
    for (int k = 0; k < 4; k++)
        xsoff[k] = ((xf + k) * PX2 + (xm >> 1)) * 2 + (xm & 1);

    float4 wr0, wr1, wr2, xr;
    {
        const float* p = wwB + c0 * (MC * JJ);
        wr0 = *(const float4*)(p + goff[0]);
        wr1 = *(const float4*)(p + goff[1]);
        wr2 = *(const float4*)(p + goff[2]);
        xr  = xact ? *(const float4*)(xB + c0 * MC * FIN + xgoff)
                   : make_float4(0.f,0.f,0.f,0.f);
    }

    for (int cc = 0; cc < CPB; ++cc) {
        ww_s[soff[0][0]] = wr0.x; ww_s[soff[0][1]] = wr0.y;
        ww_s[soff[0][2]] = wr0.z; ww_s[soff[0][3]] = wr0.w;
        ww_s[soff[1][0]] = wr1.x; ww_s[soff[1][1]] = wr1.y;
        ww_s[soff[1][2]] = wr1.z; ww_s[soff[1][3]] = wr1.w;
        ww_s[soff[2][0]] = wr2.x; ww_s[soff[2][1]] = wr2.y;
        ww_s[soff[2][2]] = wr2.z; ww_s[soff[2][3]] = wr2.w;
        if (xact) {
            float* xs = reinterpret_cast<float*>(x2_s);
            xs[xsoff[0]] = xr.x; xs[xsoff[1]] = xr.y;
            xs[xsoff[2]] = xr.z; xs[xsoff[3]] = xr.w;
        }
        __syncthreads();

        if (cc + 1 < CPB) {
            const float* p = wwB + (c0 + cc + 1) * (MC * JJ);
            wr0 = *(const float4*)(p + goff[0]);
            wr1 = *(const float4*)(p + goff[1]);
            wr2 = *(const float4*)(p + goff[2]);
            if (xact) xr = *(const float4*)(xB + (c0 + cc + 1) * MC * FIN + xgoff);
        }

#pragma unroll
        for (int mp = 0; mp < MC / 2; ++mp) {
            ull xv[4];
#pragma unroll
            for (int k = 0; k < 4; k++)
                xv[k] = x2_s[(fq + 8 * k) * PX2 + mp];
#pragma unroll
            for (int nn = 0; nn < 2; nn++) {
                const float* rp = ww_s + (nloc + nn) * PWW + 2 * mp;
                ull w0 = ld64s(rp);
                ull w1 = ld64s(rp + MC);
                ull w2 = ld64s(rp + 2 * MC);
#pragma unroll
                for (int k = 0; k < 4; k++) {
                    acc[nn][0][k] = fma2(w0, xv[k], acc[nn][0][k]);
                    acc[nn][1][k] = fma2(w1, xv[k], acc[nn][1][k]);
                    acc[nn][2][k] = fma2(w2, xv[k], acc[nn][2][k]);
                }
            }
        }
        __syncthreads();
    }

    const size_t rowbase = (size_t)blockIdx.z * ROWS + (size_t)(b * NPTS + n0);
#pragma unroll
    for (int nn = 0; nn < 2; nn++) {
        float* yr = g_yp + (rowbase + nloc + nn) * KIN;
#pragma unroll
        for (int j = 0; j < 3; j++)
#pragma unroll
            for (int k = 0; k < 4; k++)
                yr[j * FIN + fq + 8 * k] = hsum2(acc[nn][j][k]);
    }
}

// K2: sum 4 partials, MLP, write Z + BN partials. 32 rows/block -> 256 blocks.
__global__ __launch_bounds__(256) void k2_mlp(const float* __restrict__ b1,
                                              const float* __restrict__ b2,
                                              float* __restrict__ Z) {
    __shared__ __align__(16) float yT[KIN * PYT2];
    __shared__ float ps[4*FOUT], pq[4*FOUT];

    const int t = threadIdx.x;
    const int row0 = blockIdx.x * K2ROWS;

#pragma unroll
    for (int i = 0; i < 3; i++) {
        int flat = i * 256 + t;
        int r = flat / 24, k4 = flat % 24;
        size_t base = ((size_t)(row0 + r)) * KIN + k4 * 4;
        float4 v0 = *(const float4*)&g_yp[base];
        float4 v1 = *(const float4*)&g_yp[base + (size_t)ROWS*KIN];
        float4 v2 = *(const float4*)&g_yp[base + (size_t)2*ROWS*KIN];
        float4 v3 = *(const float4*)&g_yp[base + (size_t)3*ROWS*KIN];
        float4 v;
        v.x = (v0.x + v1.x) + (v2.x + v3.x);
        v.y = (v0.y + v1.y) + (v2.y + v3.y);
        v.z = (v0.z + v1.z) + (v2.z + v3.z);
        v.w = (v0.w + v1.w) + (v2.w + v3.w);
        int sb = (k4 * 4) * PYT2 + r;
        yT[sb]            = v.x;
        yT[sb +     PYT2] = v.y;
        yT[sb + 2 * PYT2] = v.z;
        yT[sb + 3 * PYT2] = v.w;
    }
    __syncthreads();

    const int col = t & 63, rg = t >> 6;
    const int rbase = rg * 8;
    ull acc2[4];
#pragma unroll
    for (int q = 0; q < 4; q++) acc2[q] = 0ULL;

#pragma unroll 4
    for (int k = 0; k < KIN; k++) {
        ull wd = dup2(__ldg(&g_wt[k * FOUT + col]));
        const float* yp = yT + k * PYT2 + rbase;
        ulonglong2 y0 = *(const ulonglong2*)(yp);
        ulonglong2 y1 = *(const ulonglong2*)(yp + 4);
        acc2[0] = fma2(y0.x, wd, acc2[0]);
        acc2[1] = fma2(y0.y, wd, acc2[1]);
        acc2[2] = fma2(y1.x, wd, acc2[2]);
        acc2[3] = fma2(y1.y, wd, acc2[3]);
    }

    const float bias = (col < 32) ? __ldg(&b1[col]) : __ldg(&b2[col - 32]);
    const size_t grow0 = (size_t)row0;
    float s = 0.f, sq = 0.f;
#pragma unroll
    for (int q = 0; q < 4; q++) {
        union { ull u; float f[2]; } cv; cv.u = acc2[q];
#pragma unroll
        for (int h = 0; h < 2; h++) {
            float z = cv.f[h] + bias;
            if (col < 32) z = fmaxf(z, 0.f);
            Z[(grow0 + rbase + 2*q + h) * FOUT + col] = z;
            s += z; sq += z * z;
        }
    }
    ps[rg * FOUT + col] = s; pq[rg * FOUT + col] = sq;
    __syncthreads();
    if (rg == 0) {   // fixed order: deterministic
        float S = (ps[col] + ps[FOUT + col]) + (ps[2*FOUT + col] + ps[3*FOUT + col]);
        float Q = (pq[col] + pq[FOUT + col]) + (pq[2*FOUT + col] + pq[3*FOUT + col]);
        g_psum[blockIdx.x * FOUT + col] = S;
        g_psq [blockIdx.x * FOUT + col] = Q;
    }
}

// K3: parallel deterministic reduce of 256 block partials -> scale/shift
__global__ void k3_stats(const float* __restrict__ gamma, const float* __restrict__ beta) {
    __shared__ float rs[16*FOUT], rq[16*FOUT];
    int t = threadIdx.x;              // 1024 threads
    int col = t & 63, seg = t >> 6;   // 16 segments x 16 blocks each
    float S = 0.f, Q = 0.f;
#pragma unroll
    for (int i = 0; i < NBLK2/16; i++) {
        int idx = (seg * (NBLK2/16) + i) * FOUT + col;
        S += g_psum[idx];
        Q += g_psq [idx];
    }
    rs[seg * FOUT + col] = S; rq[seg * FOUT + col] = Q;
    __syncthreads();
    for (int h = 8; h > 0; h >>= 1) {
        if (seg < h) {
            rs[seg * FOUT + col] += rs[(seg + h) * FOUT + col];
            rq[seg * FOUT + col] += rq[(seg + h) * FOUT + col];
        }
        __syncthreads();
    }
    if (seg == 0) {
        float mean = rs[col] * (1.0f / ROWS);
        float var  = rq[col] * (1.0f / ROWS) - mean * mean;
        float sc   = gamma[col] * rsqrtf(var + 1e-5f);
        g_coef[col]        = sc;
        g_coef[FOUT + col] = beta[col] - mean * sc;
    }
}

// K4: in-place normalize, 2 float4 per thread
__global__ __launch_bounds__(256) void k4_norm(float* __restrict__ Z) {
    int i0 = blockIdx.x * 512 + threadIdx.x;
    float4* Z4 = (float4*)Z;
    float4 v0 = Z4[i0];
    float4 v1 = Z4[i0 + 256];
    int c = (i0 & 15) * 4;          // (i0+256) has same column phase
    float s0 = g_coef[c],   s1 = g_coef[c+1], s2 = g_coef[c+2], s3 = g_coef[c+3];
    float h0 = g_coef[FOUT+c], h1 = g_coef[FOUT+c+1], h2 = g_coef[FOUT+c+2], h3 = g_coef[FOUT+c+3];
    v0.x = v0.x*s0 + h0; v0.y = v0.y*s1 + h1; v0.z = v0.z*s2 + h2; v0.w = v0.w*s3 + h3;
    v1.x = v1.x*s0 + h0; v1.y = v1.y*s1 + h1; v1.z = v1.z*s2 + h2; v1.w = v1.w*s3 + h3;
    Z4[i0] = v0;
    Z4[i0 + 256] = v1;
}

extern "C" void kernel_launch(void* const* d_in, const int* in_sizes, int n_in,
                              void* d_out, int out_size) {
    const float* WW    = (const float*)d_in[0];
    const float* X     = (const float*)d_in[1];
    const float* W1    = (const float*)d_in[2];
    const float* b1    = (const float*)d_in[3];
    const float* W2    = (const float*)d_in[4];
    const float* b2    = (const float*)d_in[5];
    const float* gamma = (const float*)d_in[6];
    const float* beta  = (const float*)d_in[7];
    float* Z = (float*)d_out;

    k0_wt<<<(KIN * FOUT + 255) / 256, 256>>>(W1, W2);
    dim3 g1(NTILE, BS, KS);
    k1_gmul<<<g1, 256>>>(WW, X);
    k2_mlp<<<NBLK2, 256>>>(b1, b2, Z);
    k3_stats<<<1, 1024>>>(gamma, beta);
    k4_norm<<<(ROWS * FOUT / 4) / 512, 256>>>(Z);
}

// round 7
// speedup vs baseline: 1.7826x; 1.4956x over previous
#include <cuda_runtime.h>
#include <cstdint>

typedef unsigned long long ull;

#define BS    8
#define NPTS  1024
#define JJ    3
#define KIN   96
#define FOUT  64
#define ROWS  (BS*NPTS)      // 8192
#define KSPL  2
#define MSEG  (NPTS/KSPL)    // 512
#define MC    32             // m per chunk
#define NCH   (MSEG/MC)      // 16
#define MT    64             // n rows per block
#define NT1   (NPTS/MT)      // 16
#define ATB   8192           // A tile bytes (64 rows x 128B)
#define BTB   4096           // B tile bytes (32 rows x 128B)
#define K2ROWS 32
#define NBLK2 (ROWS/K2ROWS)  // 256
#define PYT2  36

__device__ __align__(16) float g_yp[KSPL*ROWS*KIN];   // 6.3 MB partials
__device__ __align__(16) float g_wt[KIN*FOUT];
__device__ float g_psum[NBLK2*FOUT];
__device__ float g_psq [NBLK2*FOUT];
__device__ float g_coef[2*FOUT];

// ---------------- helpers ----------------
#define SW128(o) ((o) ^ (((o) >> 3) & 0x70))

__device__ __forceinline__ uint32_t smem_u32(const void* p) {
    uint32_t a;
    asm("{ .reg .u64 t; cvta.to.shared.u64 t, %1; cvt.u32.u64 %0, t; }" : "=r"(a) : "l"(p));
    return a;
}
// pack 2 fp32 -> bf16x2: low half = f0, high half = f1
__device__ __forceinline__ uint32_t cvt2(float f0, float f1) {
    uint32_t r;
    asm("cvt.rn.bf16x2.f32 %0, %1, %2;" : "=r"(r) : "f"(f1), "f"(f0));
    return r;
}
__device__ __forceinline__ void sts32(uint32_t a, uint32_t v) {
    asm volatile("st.shared.b32 [%0], %1;" :: "r"(a), "r"(v) : "memory");
}
__device__ __forceinline__ void sts128(uint32_t a, uint32_t v0, uint32_t v1,
                                       uint32_t v2, uint32_t v3) {
    asm volatile("st.shared.v4.b32 [%0], {%1,%2,%3,%4};"
                 :: "r"(a), "r"(v0), "r"(v1), "r"(v2), "r"(v3) : "memory");
}
__device__ __forceinline__ void ldmx4(uint32_t* r, uint32_t a) {
    asm volatile("ldmatrix.sync.aligned.m8n8.x4.shared.b16 {%0,%1,%2,%3}, [%4];"
                 : "=r"(r[0]), "=r"(r[1]), "=r"(r[2]), "=r"(r[3]) : "r"(a));
}
__device__ __forceinline__ void mma16816(float* d, const uint32_t* A, const uint32_t* B) {
    asm volatile(
        "mma.sync.aligned.m16n8k16.row.col.f32.bf16.bf16.f32 "
        "{%0,%1,%2,%3}, {%4,%5,%6,%7}, {%8,%9}, {%0,%1,%2,%3};"
        : "+f"(d[0]), "+f"(d[1]), "+f"(d[2]), "+f"(d[3])
        : "r"(A[0]), "r"(A[1]), "r"(A[2]), "r"(A[3]), "r"(B[0]), "r"(B[1]));
}
__device__ __forceinline__ ull fma2(ull a, ull b, ull c) {
    ull d;
    asm("fma.rn.f32x2 %0, %1, %2, %3;" : "=l"(d) : "l"(a), "l"(b), "l"(c));
    return d;
}
__device__ __forceinline__ ull dup2(float x) {
    unsigned b = __float_as_uint(x);
    return (((ull)b) << 32) | (ull)b;
}

// ---------------- K0: fuse/transpose weights ----------------
__global__ void k0_wt(const float* __restrict__ W1, const float* __restrict__ W2) {
    int t = blockIdx.x * 256 + threadIdx.x;
    if (t < KIN * FOUT) {
        int c = t & 63, k = t >> 6;
        g_wt[k * FOUT + c] = (c < 32) ? W1[c * KIN + k] : W2[(c - 32) * KIN + k];
    }
}

// ---------------- K1: bf16-split GMul on mma.sync ----------------
// Block: 64 n-rows of one batch, one m-half. 128 threads = 4 warps, warp = 16 rows.
// Smem per chunk: 3 A-tiles [64n x (32m hi | 32m lo) bf16] SW128,
//                 1 B-tile  [32f x (32m hi | 32m lo) bf16] SW128.
__global__ __launch_bounds__(128) void k1_gmul(const float* __restrict__ WW,
                                               const float* __restrict__ X) {
    __shared__ float4 smv[(3*ATB + BTB) / 16];
    const uint32_t sb = smem_u32(smv);
    const uint32_t Bb = sb + 3*ATB;

    const int t = threadIdx.x, warp = t >> 5, lane = t & 31;
    const int b  = blockIdx.y;
    const int n0 = blockIdx.x * MT;
    const int bz = blockIdx.z;

    const float* wwC = WW + ((size_t)(b * NPTS + n0) * NPTS + (size_t)bz * MSEG) * 3;
    const float* xC  = X + (size_t)b * NPTS * 32 + (size_t)bz * MSEG * 32;

    // WW loader: thread -> (n-row ln, m-range [mh, mh+16)); 48 consecutive floats
    const int ln = t >> 1, mh = (t & 1) * 16;
    const float* wrow = wwC + (size_t)ln * (NPTS * 3) + mh * 3;
    // X loader: m-pair mp (0..15), 4 f at xf0
    const int mp = t >> 3, xf0 = (t & 7) * 4;
    const float* xrow = xC + 2 * mp * 32 + xf0;

    // ldmatrix lane-offset components (within-tile byte offsets, pre-swizzle)
    const int rw = warp * 16;
    const uint32_t aoffL = (uint32_t)(rw + (lane & 15)) * 128 + (lane >> 4) * 16;
    const uint32_t boffL = (uint32_t)(8 * (lane >> 4) + (lane & 7)) * 128 + ((lane >> 3) & 1) * 16;

    float acc[48];   // [j][fb][4]
#pragma unroll
    for (int i = 0; i < 48; i++) acc[i] = 0.f;

    // prologue: load chunk 0
    float wf[48];
    float4 xr0, xr1;
#pragma unroll
    for (int i = 0; i < 12; i++)
        *(float4*)(wf + 4*i) = *(const float4*)(wrow + 4*i);
    xr0 = *(const float4*)(xrow);
    xr1 = *(const float4*)(xrow + 32);

    for (int c = 0; c < NCH; ++c) {
        // ---- convert + stage A tiles ----
#pragma unroll
        for (int j = 0; j < 3; j++) {
            uint32_t hw[8], lw[8];
#pragma unroll
            for (int p = 0; p < 8; p++) {
                float a0 = wf[(2*p)   * 3 + j];
                float a1 = wf[(2*p+1) * 3 + j];
                uint32_t h = cvt2(a0, a1);
                float r0 = a0 - __uint_as_float(h << 16);
                float r1 = a1 - __uint_as_float(h & 0xffff0000u);
                hw[p] = h;
                lw[p] = cvt2(r0, r1);
            }
            const uint32_t tb = sb + j * ATB;
            const uint32_t rb = (uint32_t)ln * 128 + mh * 2;
            sts128(tb + SW128(rb),      hw[0], hw[1], hw[2], hw[3]);
            sts128(tb + SW128(rb + 16), hw[4], hw[5], hw[6], hw[7]);
            sts128(tb + SW128(rb + 64), lw[0], lw[1], lw[2], lw[3]);
            sts128(tb + SW128(rb + 80), lw[4], lw[5], lw[6], lw[7]);
        }
        // ---- convert + stage B tile (x transposed: row f, col m) ----
        {
            float xa[4] = { xr0.x, xr0.y, xr0.z, xr0.w };
            float xb[4] = { xr1.x, xr1.y, xr1.z, xr1.w };
#pragma unroll
            for (int ff = 0; ff < 4; ff++) {
                uint32_t h = cvt2(xa[ff], xb[ff]);
                float r0 = xa[ff] - __uint_as_float(h << 16);
                float r1 = xb[ff] - __uint_as_float(h & 0xffff0000u);
                uint32_t l = cvt2(r0, r1);
                uint32_t fr = (uint32_t)(xf0 + ff) * 128 + 4 * mp;
                sts32(Bb + SW128(fr),      h);
                sts32(Bb + SW128(fr + 64), l);
            }
        }
        __syncthreads();

        // ---- prefetch next chunk (latency hidden by mma phase) ----
        if (c + 1 < NCH) {
            const float* wp = wrow + (c + 1) * (MC * 3);
#pragma unroll
            for (int i = 0; i < 12; i++)
                *(float4*)(wf + 4*i) = *(const float4*)(wp + 4*i);
            const float* xp = xrow + (c + 1) * (MC * 32);
            xr0 = *(const float4*)(xp);
            xr1 = *(const float4*)(xp + 32);
        }

        // ---- mma phase: 3 passes (AhBh, AhBl, AlBh) ----
#pragma unroll
        for (int ks = 0; ks < 2; ks++) {
            uint32_t Bh[8], Bl[8];
            ldmx4(Bh,     Bb + SW128(boffL + ks*32));
            ldmx4(Bh + 4, Bb + SW128(boffL + 2048 + ks*32));
            ldmx4(Bl,     Bb + SW128(boffL + 64 + ks*32));
            ldmx4(Bl + 4, Bb + SW128(boffL + 2048 + 64 + ks*32));
#pragma unroll
            for (int j = 0; j < 3; j++) {
                uint32_t Ah[4], Al[4];
                const uint32_t ab = sb + j * ATB;
                ldmx4(Ah, ab + SW128(aoffL + ks*32));
                ldmx4(Al, ab + SW128(aoffL + 64 + ks*32));
#pragma unroll
                for (int fb = 0; fb < 4; fb++) {
                    float* d = acc + j*16 + fb*4;
                    mma16816(d, Ah, Bh + 2*fb);
                    mma16816(d, Ah, Bl + 2*fb);
                    mma16816(d, Al, Bh + 2*fb);
                }
            }
        }
        __syncthreads();
    }

    // ---- epilogue: write partial y ----
    const int g = lane >> 2, tq = lane & 3;
    const size_t row = (size_t)bz * ROWS + (size_t)b * NPTS + n0 + rw + g;
    float* y0 = g_yp + row * KIN;
    float* y1 = y0 + 8 * KIN;
#pragma unroll
    for (int j = 0; j < 3; j++)
#pragma unroll
        for (int fb = 0; fb < 4; fb++) {
            const float* d = acc + j*16 + fb*4;
            const int cb = j*32 + fb*8 + 2*tq;
            float2 lo = { d[0], d[1] };
            float2 hi = { d[2], d[3] };
            *(float2*)(y0 + cb) = lo;
            *(float2*)(y1 + cb) = hi;
        }
}

// ---------------- K2: sum 2 partials, MLP, Z + BN partials ----------------
__global__ __launch_bounds__(256) void k2_mlp(const float* __restrict__ b1,
                                              const float* __restrict__ b2,
                                              float* __restrict__ Z) {
    __shared__ __align__(16) float yT[KIN * PYT2];
    __shared__ float ps[4*FOUT], pq[4*FOUT];

    const int t = threadIdx.x;
    const int row0 = blockIdx.x * K2ROWS;

#pragma unroll
    for (int i = 0; i < 3; i++) {
        int flat = i * 256 + t;
        int r = flat / 24, k4 = flat % 24;
        size_t base = ((size_t)(row0 + r)) * KIN + k4 * 4;
        float4 v0 = *(const float4*)&g_yp[base];
        float4 v1 = *(const float4*)&g_yp[base + (size_t)ROWS*KIN];
        float4 v;
        v.x = v0.x + v1.x; v.y = v0.y + v1.y;
        v.z = v0.z + v1.z; v.w = v0.w + v1.w;
        int sbi = (k4 * 4) * PYT2 + r;
        yT[sbi]            = v.x;
        yT[sbi +     PYT2] = v.y;
        yT[sbi + 2 * PYT2] = v.z;
        yT[sbi + 3 * PYT2] = v.w;
    }
    __syncthreads();

    const int col = t & 63, rg = t >> 6;
    const int rbase = rg * 8;
    ull acc2[4];
#pragma unroll
    for (int q = 0; q < 4; q++) acc2[q] = 0ULL;

#pragma unroll 4
    for (int k = 0; k < KIN; k++) {
        ull wd = dup2(__ldg(&g_wt[k * FOUT + col]));
        const float* yp = yT + k * PYT2 + rbase;
        ulonglong2 y0 = *(const ulonglong2*)(yp);
        ulonglong2 y1 = *(const ulonglong2*)(yp + 4);
        acc2[0] = fma2(y0.x, wd, acc2[0]);
        acc2[1] = fma2(y0.y, wd, acc2[1]);
        acc2[2] = fma2(y1.x, wd, acc2[2]);
        acc2[3] = fma2(y1.y, wd, acc2[3]);
    }

    const float bias = (col < 32) ? __ldg(&b1[col]) : __ldg(&b2[col - 32]);
    float s = 0.f, sq = 0.f;
#pragma unroll
    for (int q = 0; q < 4; q++) {
        union { ull u; float f[2]; } cv; cv.u = acc2[q];
#pragma unroll
        for (int h = 0; h < 2; h++) {
            float z = cv.f[h] + bias;
            if (col < 32) z = fmaxf(z, 0.f);
            Z[((size_t)row0 + rbase + 2*q + h) * FOUT + col] = z;
            s += z; sq += z * z;
        }
    }
    ps[rg * FOUT + col] = s; pq[rg * FOUT + col] = sq;
    __syncthreads();
    if (rg == 0) {
        float S = (ps[col] + ps[FOUT + col]) + (ps[2*FOUT + col] + ps[3*FOUT + col]);
        float Q = (pq[col] + pq[FOUT + col]) + (pq[2*FOUT + col] + pq[3*FOUT + col]);
        g_psum[blockIdx.x * FOUT + col] = S;
        g_psq [blockIdx.x * FOUT + col] = Q;
    }
}

// ---------------- K3: coalesced deterministic stats reduce ----------------
__global__ void k3_stats(const float* __restrict__ gamma, const float* __restrict__ beta) {
    __shared__ float4 rs4[64*16], rq4[64*16];
    const int t = threadIdx.x;           // 1024
    const int cg = t & 15, seg = t >> 4; // 16 float4-cols x 64 segs
    const float4* P = (const float4*)g_psum;
    const float4* Q = (const float4*)g_psq;
    float4 S = make_float4(0,0,0,0), Qv = make_float4(0,0,0,0);
#pragma unroll
    for (int i = 0; i < 4; i++) {
        int r = seg * 4 + i;
        float4 a = P[r * 16 + cg];
        float4 q = Q[r * 16 + cg];
        S.x += a.x; S.y += a.y; S.z += a.z; S.w += a.w;
        Qv.x += q.x; Qv.y += q.y; Qv.z += q.z; Qv.w += q.w;
    }
    rs4[seg * 16 + cg] = S; rq4[seg * 16 + cg] = Qv;
    __syncthreads();
    for (int h = 32; h > 0; h >>= 1) {
        if (seg < h) {
            float4 a = rs4[(seg + h) * 16 + cg];
            float4 q = rq4[(seg + h) * 16 + cg];
            float4 s0 = rs4[seg * 16 + cg];
            float4 q0 = rq4[seg * 16 + cg];
            s0.x += a.x; s0.y += a.y; s0.z += a.z; s0.w += a.w;
            q0.x += q.x; q0.y += q.y; q0.z += q.z; q0.w += q.w;
            rs4[seg * 16 + cg] = s0; rq4[seg * 16 + cg] = q0;
        }
        __syncthreads();
    }
    if (seg == 0) {
        float4 Sf = rs4[cg], Qf = rq4[cg];
        float sv[4] = { Sf.x, Sf.y, Sf.z, Sf.w };
        float qv[4] = { Qf.x, Qf.y, Qf.z, Qf.w };
#pragma unroll
        for (int u = 0; u < 4; u++) {
            int c = cg * 4 + u;
            float mean = sv[u] * (1.0f / ROWS);
            float var  = qv[u] * (1.0f / ROWS) - mean * mean;
            float sc   = gamma[c] * rsqrtf(var + 1e-5f);
            g_coef[c]        = sc;
            g_coef[FOUT + c] = beta[c] - mean * sc;
        }
    }
}

// ---------------- K4: in-place normalize ----------------
__global__ __launch_bounds__(256) void k4_norm(float* __restrict__ Z) {
    int i0 = blockIdx.x * 512 + threadIdx.x;
    float4* Z4 = (float4*)Z;
    float4 v0 = Z4[i0];
    float4 v1 = Z4[i0 + 256];
    int c = (i0 & 15) * 4;
    float s0 = g_coef[c],   s1 = g_coef[c+1], s2 = g_coef[c+2], s3 = g_coef[c+3];
    float h0 = g_coef[FOUT+c], h1 = g_coef[FOUT+c+1], h2 = g_coef[FOUT+c+2], h3 = g_coef[FOUT+c+3];
    v0.x = v0.x*s0 + h0; v0.y = v0.y*s1 + h1; v0.z = v0.z*s2 + h2; v0.w = v0.w*s3 + h3;
    v1.x = v1.x*s0 + h0; v1.y = v1.y*s1 + h1; v1.z = v1.z*s2 + h2; v1.w = v1.w*s3 + h3;
    Z4[i0] = v0;
    Z4[i0 + 256] = v1;
}

extern "C" void kernel_launch(void* const* d_in, const int* in_sizes, int n_in,
                              void* d_out, int out_size) {
    const float* WW    = (const float*)d_in[0];
    const float* X     = (const float*)d_in[1];
    const float* W1    = (const float*)d_in[2];
    const float* b1    = (const float*)d_in[3];
    const float* W2    = (const float*)d_in[4];
    const float* b2    = (const float*)d_in[5];
    const float* gamma = (const float*)d_in[6];
    const float* beta  = (const float*)d_in[7];
    float* Z = (float*)d_out;

    k0_wt<<<(KIN * FOUT + 255) / 256, 256>>>(W1, W2);
    dim3 g1(NT1, BS, KSPL);
    k1_gmul<<<g1, 128>>>(WW, X);
    k2_mlp<<<NBLK2, 256>>>(b1, b2, Z);
    k3_stats<<<1, 1024>>>(gamma, beta);
    k4_norm<<<(ROWS * FOUT / 4) / 512, 256>>>(Z);
}